// round 1
// baseline (speedup 1.0000x reference)
#include <cuda_runtime.h>

// Problem constants
#define N_ROWS 8192
#define HDIM   1024
#define B0DIM  64
#define FDIM   2048
#define ODIM   2048
#define XDIM   (HDIM + B0DIM + FDIM)   // 3136
#define NB     6

// -------------------- scratch (device globals; no allocs allowed) ---------
__device__ float g_q   [N_ROWS * FDIM];
__device__ float g_sumq[N_ROWS * FDIM];
__device__ float g_rS  [N_ROWS * FDIM];
__device__ float g_t   [N_ROWS * FDIM];
__device__ float g_Aq  [N_ROWS * FDIM];
__device__ float g_sumh[N_ROWS * HDIM];
__device__ float g_rqh [N_ROWS * HDIM];
__device__ float g_Dh  [N_ROWS * HDIM];
__device__ float g_h   [N_ROWS * HDIM];
__device__ float g_th  [N_ROWS * HDIM];

// -------------------- tiled SGEMM: C = epi(A[M,K] @ W[Fout,K]^T + bias) ---
// MODE 0: C = acc + b
// MODE 1: C = relu(acc + b)
// MODE 2: C = C + acc + b          (accumulate into existing C)
// MODE 3: C = C - leaky(acc + b)   (leaky slope = a_ptr[0])
// BM=BN=128, BK=8, 256 threads, 8x8 per-thread tile. All dims divide evenly.
template <int MODE>
__global__ __launch_bounds__(256, 2) void sgemm_k(
    const float* __restrict__ A, int lda,
    const float* __restrict__ W,           // row-major [Fout, K], ldw = K
    const float* __restrict__ bias,        // [Fout]
    float* __restrict__ C, int ldc,
    int K,
    const float* __restrict__ a_ptr)
{
    __shared__ float As[8][128];
    __shared__ float Bs[8][128];

    const int t    = threadIdx.x;
    const int tx   = t & 15;        // 0..15 -> n
    const int ty   = t >> 4;        // 0..15 -> m
    const int brow = blockIdx.y * 128;
    const int bcol = blockIdx.x * 128;

    const int lrow = t >> 1;        // 0..127
    const int lk   = (t & 1) * 4;   // 0 or 4

    const float* Ap = A + (size_t)(brow + lrow) * lda + lk;
    const float* Wp = W + (size_t)(bcol + lrow) * K   + lk;

    float c[8][8];
#pragma unroll
    for (int i = 0; i < 8; i++)
#pragma unroll
        for (int j = 0; j < 8; j++) c[i][j] = 0.f;

    for (int k0 = 0; k0 < K; k0 += 8) {
        const float4 av = *(const float4*)(Ap + k0);
        const float4 wv = *(const float4*)(Wp + k0);
        __syncthreads();
        As[lk + 0][lrow] = av.x; As[lk + 1][lrow] = av.y;
        As[lk + 2][lrow] = av.z; As[lk + 3][lrow] = av.w;
        Bs[lk + 0][lrow] = wv.x; Bs[lk + 1][lrow] = wv.y;
        Bs[lk + 2][lrow] = wv.z; Bs[lk + 3][lrow] = wv.w;
        __syncthreads();
#pragma unroll
        for (int kk = 0; kk < 8; kk++) {
            float a[8], b[8];
            *(float4*)&a[0] = *(const float4*)&As[kk][ty * 8];
            *(float4*)&a[4] = *(const float4*)&As[kk][ty * 8 + 4];
            *(float4*)&b[0] = *(const float4*)&Bs[kk][tx * 8];
            *(float4*)&b[4] = *(const float4*)&Bs[kk][tx * 8 + 4];
#pragma unroll
            for (int i = 0; i < 8; i++)
#pragma unroll
                for (int j = 0; j < 8; j++)
                    c[i][j] += a[i] * b[j];
        }
    }

    float alpha = 0.f;
    if (MODE == 3) alpha = a_ptr[0];

    float bv[8];
#pragma unroll
    for (int j = 0; j < 8; j++) bv[j] = bias[bcol + tx * 8 + j];

#pragma unroll
    for (int i = 0; i < 8; i++) {
        float* Crow = C + (size_t)(brow + ty * 8 + i) * ldc + bcol + tx * 8;
        float out[8];
#pragma unroll
        for (int j = 0; j < 8; j++) {
            float v = c[i][j] + bv[j];
            if (MODE == 1) v = v > 0.f ? v : 0.f;
            if (MODE == 2) v = Crow[j] + v;
            if (MODE == 3) {
                float l = (v >= 0.f) ? v : alpha * v;
                v = Crow[j] - l;
            }
            out[j] = v;
        }
        *(float4*)(Crow)     = *(const float4*)&out[0];
        *(float4*)(Crow + 4) = *(const float4*)&out[4];
    }
}

// -------------------- elementwise kernels (float4 vectorized) -------------
// q = (pi/4) * d^2, d = x[:, H+B0 : H+B0+F]  (strided source)
__global__ __launch_bounds__(256) void k_square(const float* __restrict__ x,
                                                float* __restrict__ q)
{
    const int i = blockIdx.x * blockDim.x + threadIdx.x;   // over N*F/4
    const int row = i / (FDIM / 4);
    const int c4  = i % (FDIM / 4);
    const float4 d = *(const float4*)(x + (size_t)row * XDIM + HDIM + B0DIM + c4 * 4);
    const float s = 0.78539816339744830962f;
    float4 o;
    o.x = s * d.x * d.x; o.y = s * d.y * d.y;
    o.z = s * d.z * d.z; o.w = s * d.w * d.w;
    *(float4*)(q + (size_t)row * FDIM + c4 * 4) = o;
}

// t = q * rS
__global__ __launch_bounds__(256) void k_mul(const float* __restrict__ a,
                                             const float* __restrict__ b,
                                             float* __restrict__ o)
{
    const int i = blockIdx.x * blockDim.x + threadIdx.x;
    const float4 av = ((const float4*)a)[i];
    const float4 bv = ((const float4*)b)[i];
    float4 ov;
    ov.x = av.x * bv.x; ov.y = av.y * bv.y;
    ov.z = av.z * bv.z; ov.w = av.w * bv.w;
    ((float4*)o)[i] = ov;
}

// t = Aq * (q + sumq)
__global__ __launch_bounds__(256) void k_hid(const float* __restrict__ Aq,
                                             const float* __restrict__ q,
                                             const float* __restrict__ sumq,
                                             float* __restrict__ o)
{
    const int i = blockIdx.x * blockDim.x + threadIdx.x;
    const float4 a = ((const float4*)Aq)[i];
    const float4 b = ((const float4*)q)[i];
    const float4 c = ((const float4*)sumq)[i];
    float4 ov;
    ov.x = a.x * (b.x + c.x); ov.y = a.y * (b.y + c.y);
    ov.z = a.z * (b.z + c.z); ov.w = a.w * (b.w + c.w);
    ((float4*)o)[i] = ov;
}

// th = (h + sumh + rqh) * Dh
__global__ __launch_bounds__(256) void k_comb(const float* __restrict__ h,
                                              const float* __restrict__ sumh,
                                              const float* __restrict__ rqh,
                                              const float* __restrict__ Dh,
                                              float* __restrict__ o)
{
    const int i = blockIdx.x * blockDim.x + threadIdx.x;
    const float4 a = ((const float4*)h)[i];
    const float4 b = ((const float4*)sumh)[i];
    const float4 c = ((const float4*)rqh)[i];
    const float4 d = ((const float4*)Dh)[i];
    float4 ov;
    ov.x = (a.x + b.x + c.x) * d.x; ov.y = (a.y + b.y + c.y) * d.y;
    ov.z = (a.z + b.z + c.z) * d.z; ov.w = (a.w + b.w + c.w) * d.w;
    ((float4*)o)[i] = ov;
}

// -------------------- driver ----------------------------------------------
extern "C" void kernel_launch(void* const* d_in, const int* in_sizes, int n_in,
                              void* d_out, int out_size)
{
    const float* x      = (const float*)d_in[0];
    const float* W_h0q  = (const float*)d_in[1];
    const float* b_h0q  = (const float*)d_in[2];
    const float* W_sq   = (const float*)d_in[3];
    const float* b_sq   = (const float*)d_in[4];
    const float* W_h0h  = (const float*)d_in[5];
    const float* b_h0h  = (const float*)d_in[6];
    const float* W_S    = (const float*)d_in[7];
    const float* b_S    = (const float*)d_in[8];
    const float* W_q0h  = (const float*)d_in[9];
    const float* b_q0h  = (const float*)d_in[10];
    const float* Wb_Aq  = (const float*)d_in[11];
    const float* bb_Aq  = (const float*)d_in[12];
    const float* Wb_Dh  = (const float*)d_in[13];
    const float* bb_Dh  = (const float*)d_in[14];
    const float* Wb_fh  = (const float*)d_in[15];
    const float* bb_fh  = (const float*)d_in[16];
    const float* Wb_hf  = (const float*)d_in[17];
    const float* bb_hf  = (const float*)d_in[18];
    const float* a_hf   = (const float*)d_in[19];
    const float* Wb_resq= (const float*)d_in[20];
    const float* bb_resq= (const float*)d_in[21];
    const float* W_out  = (const float*)d_in[22];
    const float* b_out  = (const float*)d_in[23];

    float *q, *sumq, *rS, *tb, *Aq, *sumh, *rqh, *Dh, *hb, *th;
    cudaGetSymbolAddress((void**)&q,    g_q);
    cudaGetSymbolAddress((void**)&sumq, g_sumq);
    cudaGetSymbolAddress((void**)&rS,   g_rS);
    cudaGetSymbolAddress((void**)&tb,   g_t);
    cudaGetSymbolAddress((void**)&Aq,   g_Aq);
    cudaGetSymbolAddress((void**)&sumh, g_sumh);
    cudaGetSymbolAddress((void**)&rqh,  g_rqh);
    cudaGetSymbolAddress((void**)&Dh,   g_Dh);
    cudaGetSymbolAddress((void**)&hb,   g_h);
    cudaGetSymbolAddress((void**)&th,   g_th);

    const dim3 gF(FDIM / 128, N_ROWS / 128);   // (16, 64)
    const dim3 gH(HDIM / 128, N_ROWS / 128);   // (8, 64)
    const int ewF = (N_ROWS * FDIM / 4) / 256; // 16384 blocks
    const int ewH = (N_ROWS * HDIM / 4) / 256; // 8192 blocks

    // ---- prologue ----
    // sum_q_const = h0 @ W_h0q^T + b  +  s @ W_sq^T + b
    sgemm_k<0><<<gF, 256>>>(x + HDIM, XDIM, W_h0q, b_h0q, sumq, FDIM, B0DIM, nullptr);
    sgemm_k<2><<<gF, 256>>>(x,        XDIM, W_sq,  b_sq,  sumq, FDIM, HDIM,  nullptr);
    // sum_h_const = h0 @ W_h0h^T + b
    sgemm_k<0><<<gH, 256>>>(x + HDIM, XDIM, W_h0h, b_h0h, sumh, HDIM, B0DIM, nullptr);
    // res_S_q = relu(d @ W_S^T + b)
    sgemm_k<1><<<gF, 256>>>(x + HDIM + B0DIM, XDIM, W_S, b_S, rS, FDIM, FDIM, nullptr);
    // q = pi/4 * d^2
    k_square<<<ewF, 256>>>(x, q);
    // res_q_h = q @ W_q0h^T + b
    sgemm_k<0><<<gH, 256>>>(q, FDIM, W_q0h, b_q0h, rqh, HDIM, FDIM, nullptr);

    // ---- 6 unrolled blocks ----
    for (int nb = 0; nb < NB; nb++) {
        const float* wAq   = Wb_Aq   + (size_t)nb * FDIM * FDIM;
        const float* bAq   = bb_Aq   + (size_t)nb * FDIM;
        const float* wDh   = Wb_Dh   + (size_t)nb * HDIM * FDIM;
        const float* bDh   = bb_Dh   + (size_t)nb * HDIM;
        const float* wfh   = Wb_fh   + (size_t)nb * HDIM * FDIM;
        const float* bfh   = bb_fh   + (size_t)nb * HDIM;
        const float* whf   = Wb_hf   + (size_t)nb * FDIM * HDIM;
        const float* bhf   = bb_hf   + (size_t)nb * FDIM;
        const float* wresq = Wb_resq + (size_t)nb * HDIM * FDIM;
        const float* bresq = bb_resq + (size_t)nb * HDIM;

        // t = q * res_S_q ; A_q = t @ W_Aq^T + b
        k_mul<<<ewF, 256>>>(q, rS, tb);
        sgemm_k<0><<<gF, 256>>>(tb, FDIM, wAq, bAq, Aq, FDIM, FDIM, nullptr);
        // D_h = relu(A_q @ W_Dh^T + b)
        sgemm_k<1><<<gH, 256>>>(Aq, FDIM, wDh, bDh, Dh, HDIM, FDIM, nullptr);
        // hid = A_q * (q + sum_q_const) ; h = relu(hid @ W_fh^T + b)
        k_hid<<<ewF, 256>>>(Aq, q, sumq, tb);
        sgemm_k<1><<<gH, 256>>>(tb, FDIM, wfh, bfh, hb, HDIM, FDIM, nullptr);
        // th = (h + sum_h_const + res_q_h) * D_h
        k_comb<<<ewH, 256>>>(hb, sumh, rqh, Dh, th);
        // z = th @ W_hf^T + b ; q = q - leaky(z, a)
        sgemm_k<3><<<gF, 256>>>(th, HDIM, whf, bhf, q, FDIM, HDIM, a_hf + nb);
        // res_q_h = relu(q @ W_resq^T + b)
        sgemm_k<1><<<gH, 256>>>(q, FDIM, wresq, bresq, rqh, HDIM, FDIM, nullptr);
    }

    // ---- output ----
    sgemm_k<0><<<gF, 256>>>(q, FDIM, W_out, b_out, (float*)d_out, ODIM, FDIM, nullptr);
}

// round 2
// speedup vs baseline: 2.2595x; 2.2595x over previous
#include <cuda_runtime.h>
#include <cuda_bf16.h>
#include <cstdint>

// Problem constants
#define N_ROWS 8192
#define HDIM   1024
#define B0DIM  64
#define FDIM   2048
#define ODIM   2048
#define XDIM   (HDIM + B0DIM + FDIM)   // 3136
#define NB     6

#define BM 128
#define BN 128
#define BK 32
#define SSTR 40   // bf16 elements per smem row (80B) -> conflict-free ldmatrix

// -------------------- scratch (device globals; no allocs allowed) ---------
__device__ float g_q   [N_ROWS * FDIM];
__device__ float g_sumq[N_ROWS * FDIM];
__device__ float g_rS  [N_ROWS * FDIM];
__device__ float g_t   [N_ROWS * FDIM];
__device__ float g_Aq  [N_ROWS * FDIM];
__device__ float g_sumh[N_ROWS * HDIM];
__device__ float g_rqh [N_ROWS * HDIM];
__device__ float g_Dh  [N_ROWS * HDIM];
__device__ float g_h   [N_ROWS * HDIM];
__device__ float g_th  [N_ROWS * HDIM];

// -------------------- helpers ---------------------------------------------
__device__ __forceinline__ void ldsm_x4(uint32_t& r0, uint32_t& r1,
                                        uint32_t& r2, uint32_t& r3,
                                        uint32_t addr)
{
    asm volatile("ldmatrix.sync.aligned.m8n8.x4.shared.b16 {%0,%1,%2,%3}, [%4];"
                 : "=r"(r0), "=r"(r1), "=r"(r2), "=r"(r3) : "r"(addr));
}

__device__ __forceinline__ void mma16816(float* c, const uint32_t* a,
                                         uint32_t b0, uint32_t b1)
{
    asm volatile(
        "mma.sync.aligned.m16n8k16.row.col.f32.bf16.bf16.f32 "
        "{%0,%1,%2,%3}, {%4,%5,%6,%7}, {%8,%9}, {%0,%1,%2,%3};"
        : "+f"(c[0]), "+f"(c[1]), "+f"(c[2]), "+f"(c[3])
        : "r"(a[0]), "r"(a[1]), "r"(a[2]), "r"(a[3]), "r"(b0), "r"(b1));
}

// split two floats into packed bf16 hi-pair and lo-pair (k ascending in low half)
__device__ __forceinline__ void cvt2(float x, float y, uint32_t& hi, uint32_t& lo)
{
    __nv_bfloat16 hx = __float2bfloat16(x);
    __nv_bfloat16 hy = __float2bfloat16(y);
    __nv_bfloat16 lx = __float2bfloat16(x - __bfloat162float(hx));
    __nv_bfloat16 ly = __float2bfloat16(y - __bfloat162float(hy));
    hi = (uint32_t(__bfloat16_as_ushort(hy)) << 16) | __bfloat16_as_ushort(hx);
    lo = (uint32_t(__bfloat16_as_ushort(ly)) << 16) | __bfloat16_as_ushort(lx);
}

// -------------------- bf16x3 tensor-core GEMM -----------------------------
// C = epi(A[M,K] @ W[Fout,K]^T + bias)
// MODE 0: C = acc + b
// MODE 1: C = relu(acc + b)
// MODE 2: C = C + acc + b
// MODE 3: C = C - leaky(acc + b)   (slope = a_ptr[0])
template <int MODE>
__global__ __launch_bounds__(256, 2) void gemm_bf16x3(
    const float* __restrict__ A, int lda,
    const float* __restrict__ W,          // [Fout, K] row-major
    const float* __restrict__ bias,       // [Fout]
    float* __restrict__ C, int ldc,
    int K,
    const float* __restrict__ a_ptr)
{
    __shared__ __nv_bfloat16 sAhi[BM * SSTR];
    __shared__ __nv_bfloat16 sAlo[BM * SSTR];
    __shared__ __nv_bfloat16 sBhi[BN * SSTR];
    __shared__ __nv_bfloat16 sBlo[BN * SSTR];

    const int t    = threadIdx.x;
    const int lane = t & 31;
    const int warp = t >> 5;
    const int wm   = warp >> 1;      // 0..3
    const int wn   = warp & 1;       // 0..1
    const int m0   = wm * 32;        // warp tile 32x64
    const int n0   = wn * 64;
    const int brow = blockIdx.y * BM;
    const int bcol = blockIdx.x * BN;

    // load mapping: thread -> (row = t/2, k-half = (t&1)*16), 16 floats each
    const int lrow = t >> 1;
    const int lk   = (t & 1) * 16;
    const float* Ap = A + (size_t)(brow + lrow) * lda + lk;
    const float* Wp = W + (size_t)(bcol + lrow) * K   + lk;

    __nv_bfloat16* saHi = sAhi + lrow * SSTR + lk;
    __nv_bfloat16* saLo = sAlo + lrow * SSTR + lk;
    __nv_bfloat16* sbHi = sBhi + lrow * SSTR + lk;
    __nv_bfloat16* sbLo = sBlo + lrow * SSTR + lk;

    float acc[2][8][4];
#pragma unroll
    for (int mt = 0; mt < 2; mt++)
#pragma unroll
        for (int nt = 0; nt < 8; nt++)
#pragma unroll
            for (int i = 0; i < 4; i++) acc[mt][nt][i] = 0.f;

    const uint32_t baseAhi = (uint32_t)__cvta_generic_to_shared(sAhi);
    const uint32_t baseAlo = (uint32_t)__cvta_generic_to_shared(sAlo);
    const uint32_t baseBhi = (uint32_t)__cvta_generic_to_shared(sBhi);
    const uint32_t baseBlo = (uint32_t)__cvta_generic_to_shared(sBlo);

    // per-lane ldmatrix address offsets (elements)
    const int aoffA = (m0 + (lane & 15)) * SSTR + ((lane >> 4) << 3);
    const int aoffB = (n0 + (lane & 7) + ((lane >> 4) << 3)) * SSTR + (((lane >> 3) & 1) << 3);

    for (int k0 = 0; k0 < K; k0 += BK) {
        // ---- global loads ----
        float4 av[4], wv[4];
#pragma unroll
        for (int i = 0; i < 4; i++) {
            av[i] = *(const float4*)(Ap + k0 + i * 4);
            wv[i] = *(const float4*)(Wp + k0 + i * 4);
        }
        __syncthreads();
        // ---- convert + store to smem ----
#pragma unroll
        for (int i = 0; i < 4; i++) {
            uint32_t h0, l0, h1, l1;
            cvt2(av[i].x, av[i].y, h0, l0);
            cvt2(av[i].z, av[i].w, h1, l1);
            *(uint2*)(saHi + i * 4) = make_uint2(h0, h1);
            *(uint2*)(saLo + i * 4) = make_uint2(l0, l1);
            cvt2(wv[i].x, wv[i].y, h0, l0);
            cvt2(wv[i].z, wv[i].w, h1, l1);
            *(uint2*)(sbHi + i * 4) = make_uint2(h0, h1);
            *(uint2*)(sbLo + i * 4) = make_uint2(l0, l1);
        }
        __syncthreads();

        // ---- 3 passes: hi*hi, hi*lo, lo*hi ----
#pragma unroll
        for (int p = 0; p < 3; p++) {
            const uint32_t abase = (p == 2) ? baseAlo : baseAhi;
            const uint32_t bbase = (p == 1) ? baseBlo : baseBhi;
#pragma unroll
            for (int kk = 0; kk < BK; kk += 16) {
                uint32_t a[2][4];
#pragma unroll
                for (int mt = 0; mt < 2; mt++)
                    ldsm_x4(a[mt][0], a[mt][1], a[mt][2], a[mt][3],
                            abase + (uint32_t)(aoffA + mt * 16 * SSTR + kk) * 2u);
                uint32_t b[4][4];
#pragma unroll
                for (int g = 0; g < 4; g++)
                    ldsm_x4(b[g][0], b[g][1], b[g][2], b[g][3],
                            bbase + (uint32_t)(aoffB + g * 16 * SSTR + kk) * 2u);
#pragma unroll
                for (int mt = 0; mt < 2; mt++)
#pragma unroll
                    for (int nt = 0; nt < 8; nt++)
                        mma16816(acc[mt][nt], a[mt],
                                 b[nt >> 1][(nt & 1) * 2],
                                 b[nt >> 1][(nt & 1) * 2 + 1]);
            }
        }
    }

    // ---- epilogue ----
    const float alpha = (MODE == 3) ? a_ptr[0] : 0.f;
#pragma unroll
    for (int mt = 0; mt < 2; mt++) {
#pragma unroll
        for (int half = 0; half < 2; half++) {
            const int row = brow + m0 + mt * 16 + (lane >> 2) + half * 8;
            float* Crow = C + (size_t)row * ldc + bcol + n0 + (lane & 3) * 2;
            const float* brow_b = bias + bcol + n0 + (lane & 3) * 2;
#pragma unroll
            for (int nt = 0; nt < 8; nt++) {
                float v0 = acc[mt][nt][half * 2 + 0] + brow_b[nt * 8 + 0];
                float v1 = acc[mt][nt][half * 2 + 1] + brow_b[nt * 8 + 1];
                if (MODE == 1) {
                    v0 = v0 > 0.f ? v0 : 0.f;
                    v1 = v1 > 0.f ? v1 : 0.f;
                }
                if (MODE == 2) {
                    float2 old = *(float2*)(Crow + nt * 8);
                    v0 += old.x; v1 += old.y;
                }
                if (MODE == 3) {
                    float2 old = *(float2*)(Crow + nt * 8);
                    float l0 = (v0 >= 0.f) ? v0 : alpha * v0;
                    float l1 = (v1 >= 0.f) ? v1 : alpha * v1;
                    v0 = old.x - l0; v1 = old.y - l1;
                }
                *(float2*)(Crow + nt * 8) = make_float2(v0, v1);
            }
        }
    }
}

// -------------------- elementwise kernels (float4 vectorized) -------------
__global__ __launch_bounds__(256) void k_square(const float* __restrict__ x,
                                                float* __restrict__ q)
{
    const int i = blockIdx.x * blockDim.x + threadIdx.x;
    const int row = i / (FDIM / 4);
    const int c4  = i % (FDIM / 4);
    const float4 d = *(const float4*)(x + (size_t)row * XDIM + HDIM + B0DIM + c4 * 4);
    const float s = 0.78539816339744830962f;
    float4 o;
    o.x = s * d.x * d.x; o.y = s * d.y * d.y;
    o.z = s * d.z * d.z; o.w = s * d.w * d.w;
    *(float4*)(q + (size_t)row * FDIM + c4 * 4) = o;
}

__global__ __launch_bounds__(256) void k_mul(const float* __restrict__ a,
                                             const float* __restrict__ b,
                                             float* __restrict__ o)
{
    const int i = blockIdx.x * blockDim.x + threadIdx.x;
    const float4 av = ((const float4*)a)[i];
    const float4 bv = ((const float4*)b)[i];
    float4 ov;
    ov.x = av.x * bv.x; ov.y = av.y * bv.y;
    ov.z = av.z * bv.z; ov.w = av.w * bv.w;
    ((float4*)o)[i] = ov;
}

__global__ __launch_bounds__(256) void k_hid(const float* __restrict__ Aq,
                                             const float* __restrict__ q,
                                             const float* __restrict__ sumq,
                                             float* __restrict__ o)
{
    const int i = blockIdx.x * blockDim.x + threadIdx.x;
    const float4 a = ((const float4*)Aq)[i];
    const float4 b = ((const float4*)q)[i];
    const float4 c = ((const float4*)sumq)[i];
    float4 ov;
    ov.x = a.x * (b.x + c.x); ov.y = a.y * (b.y + c.y);
    ov.z = a.z * (b.z + c.z); ov.w = a.w * (b.w + c.w);
    ((float4*)o)[i] = ov;
}

__global__ __launch_bounds__(256) void k_comb(const float* __restrict__ h,
                                              const float* __restrict__ sumh,
                                              const float* __restrict__ rqh,
                                              const float* __restrict__ Dh,
                                              float* __restrict__ o)
{
    const int i = blockIdx.x * blockDim.x + threadIdx.x;
    const float4 a = ((const float4*)h)[i];
    const float4 b = ((const float4*)sumh)[i];
    const float4 c = ((const float4*)rqh)[i];
    const float4 d = ((const float4*)Dh)[i];
    float4 ov;
    ov.x = (a.x + b.x + c.x) * d.x; ov.y = (a.y + b.y + c.y) * d.y;
    ov.z = (a.z + b.z + c.z) * d.z; ov.w = (a.w + b.w + c.w) * d.w;
    ((float4*)o)[i] = ov;
}

// -------------------- driver ----------------------------------------------
extern "C" void kernel_launch(void* const* d_in, const int* in_sizes, int n_in,
                              void* d_out, int out_size)
{
    const float* x      = (const float*)d_in[0];
    const float* W_h0q  = (const float*)d_in[1];
    const float* b_h0q  = (const float*)d_in[2];
    const float* W_sq   = (const float*)d_in[3];
    const float* b_sq   = (const float*)d_in[4];
    const float* W_h0h  = (const float*)d_in[5];
    const float* b_h0h  = (const float*)d_in[6];
    const float* W_S    = (const float*)d_in[7];
    const float* b_S    = (const float*)d_in[8];
    const float* W_q0h  = (const float*)d_in[9];
    const float* b_q0h  = (const float*)d_in[10];
    const float* Wb_Aq  = (const float*)d_in[11];
    const float* bb_Aq  = (const float*)d_in[12];
    const float* Wb_Dh  = (const float*)d_in[13];
    const float* bb_Dh  = (const float*)d_in[14];
    const float* Wb_fh  = (const float*)d_in[15];
    const float* bb_fh  = (const float*)d_in[16];
    const float* Wb_hf  = (const float*)d_in[17];
    const float* bb_hf  = (const float*)d_in[18];
    const float* a_hf   = (const float*)d_in[19];
    const float* Wb_resq= (const float*)d_in[20];
    const float* bb_resq= (const float*)d_in[21];
    const float* W_out  = (const float*)d_in[22];
    const float* b_out  = (const float*)d_in[23];

    float *q, *sumq, *rS, *tb, *Aq, *sumh, *rqh, *Dh, *hb, *th;
    cudaGetSymbolAddress((void**)&q,    g_q);
    cudaGetSymbolAddress((void**)&sumq, g_sumq);
    cudaGetSymbolAddress((void**)&rS,   g_rS);
    cudaGetSymbolAddress((void**)&tb,   g_t);
    cudaGetSymbolAddress((void**)&Aq,   g_Aq);
    cudaGetSymbolAddress((void**)&sumh, g_sumh);
    cudaGetSymbolAddress((void**)&rqh,  g_rqh);
    cudaGetSymbolAddress((void**)&Dh,   g_Dh);
    cudaGetSymbolAddress((void**)&hb,   g_h);
    cudaGetSymbolAddress((void**)&th,   g_th);

    const dim3 gF(FDIM / BN, N_ROWS / BM);   // (16, 64)
    const dim3 gH(HDIM / BN, N_ROWS / BM);   // (8, 64)
    const int ewF = (N_ROWS * FDIM / 4) / 256;
    const int ewH = (N_ROWS * HDIM / 4) / 256;

    // ---- prologue ----
    gemm_bf16x3<0><<<gF, 256>>>(x + HDIM, XDIM, W_h0q, b_h0q, sumq, FDIM, B0DIM, nullptr);
    gemm_bf16x3<2><<<gF, 256>>>(x,        XDIM, W_sq,  b_sq,  sumq, FDIM, HDIM,  nullptr);
    gemm_bf16x3<0><<<gH, 256>>>(x + HDIM, XDIM, W_h0h, b_h0h, sumh, HDIM, B0DIM, nullptr);
    gemm_bf16x3<1><<<gF, 256>>>(x + HDIM + B0DIM, XDIM, W_S, b_S, rS, FDIM, FDIM, nullptr);
    k_square<<<ewF, 256>>>(x, q);
    gemm_bf16x3<0><<<gH, 256>>>(q, FDIM, W_q0h, b_q0h, rqh, HDIM, FDIM, nullptr);

    // ---- 6 unrolled blocks ----
    for (int nb = 0; nb < NB; nb++) {
        const float* wAq   = Wb_Aq   + (size_t)nb * FDIM * FDIM;
        const float* bAq   = bb_Aq   + (size_t)nb * FDIM;
        const float* wDh   = Wb_Dh   + (size_t)nb * HDIM * FDIM;
        const float* bDh   = bb_Dh   + (size_t)nb * HDIM;
        const float* wfh   = Wb_fh   + (size_t)nb * HDIM * FDIM;
        const float* bfh   = bb_fh   + (size_t)nb * HDIM;
        const float* whf   = Wb_hf   + (size_t)nb * FDIM * HDIM;
        const float* bhf   = bb_hf   + (size_t)nb * FDIM;
        const float* wresq = Wb_resq + (size_t)nb * HDIM * FDIM;
        const float* bresq = bb_resq + (size_t)nb * HDIM;

        k_mul<<<ewF, 256>>>(q, rS, tb);
        gemm_bf16x3<0><<<gF, 256>>>(tb, FDIM, wAq, bAq, Aq, FDIM, FDIM, nullptr);
        gemm_bf16x3<1><<<gH, 256>>>(Aq, FDIM, wDh, bDh, Dh, HDIM, FDIM, nullptr);
        k_hid<<<ewF, 256>>>(Aq, q, sumq, tb);
        gemm_bf16x3<1><<<gH, 256>>>(tb, FDIM, wfh, bfh, hb, HDIM, FDIM, nullptr);
        k_comb<<<ewH, 256>>>(hb, sumh, rqh, Dh, th);
        gemm_bf16x3<3><<<gF, 256>>>(th, HDIM, whf, bhf, q, FDIM, HDIM, a_hf + nb);
        gemm_bf16x3<1><<<gH, 256>>>(q, FDIM, wresq, bresq, rqh, HDIM, FDIM, nullptr);
    }

    // ---- output ----
    gemm_bf16x3<0><<<gF, 256>>>(q, FDIM, W_out, b_out, (float*)d_out, ODIM, FDIM, nullptr);
}